// round 9
// baseline (speedup 1.0000x reference)
#include <cuda_runtime.h>
#include <cuda_bf16.h>
#include <cstdint>

// ---------------------------------------------------------------------------
// Problem constants
// ---------------------------------------------------------------------------
#define B_    8
#define NH    8
#define HD    48
#define HW    64
#define NPIX  4096            // 64*64
#define C_    384
#define M_    32768           // B_*NPIX
#define L_    277             // 1 + 4 + 16 + 256
#define LP    288             // padded L (9 chunks of 32)
#define QKN   1152            // 3*C_
#define MP_   (B_ * LP)       // 2304 pooled rows (padded)

// scale * log2(e), folded into the q-columns of w_qkv at conversion time
#define QSC   0.2082351519f

// ---------------------------------------------------------------------------
// Scratch (allocation-free rule: __device__ globals; zero-initialized)
// ---------------------------------------------------------------------------
__device__ float g_xp[MP_ * C_];               // pooled x: only s16 rows (21..276) written

__device__ __nv_bfloat16 g_qhi[M_ * C_];       // q (pre-scaled), split
__device__ __nv_bfloat16 g_qlo[M_ * C_];
__device__ __nv_bfloat16 g_xhi[M_ * C_];
__device__ __nv_bfloat16 g_xlo[M_ * C_];
__device__ __nv_bfloat16 g_xphi[MP_ * C_];     // pooled x, split (pad rows = 0)
__device__ __nv_bfloat16 g_xplo[MP_ * C_];
__device__ __nv_bfloat16 g_wqT_hi[QKN * C_];   // w_qkv transposed: [1152, 384]
__device__ __nv_bfloat16 g_wqT_lo[QKN * C_];
__device__ __nv_bfloat16 g_wpT_hi[C_ * C_];    // w_proj transposed: [384, 384]
__device__ __nv_bfloat16 g_wpT_lo[C_ * C_];
__device__ __nv_bfloat16 g_aohi[M_ * C_];      // attention output, split
__device__ __nv_bfloat16 g_aolo[M_ * C_];

__device__ __nv_bfloat16 g_kphi[B_ * NH * LP * HD];   // [bh][l(288)][d]
__device__ __nv_bfloat16 g_kplo[B_ * NH * LP * HD];
__device__ __nv_bfloat16 g_vpthi[B_ * NH * HD * LP];  // [bh][d][l(288)]
__device__ __nv_bfloat16 g_vptlo[B_ * NH * HD * LP];

// ---------------------------------------------------------------------------
// PTX helpers (sm_80+ only; no 'a'-suffix features)
// ---------------------------------------------------------------------------
__device__ __forceinline__ uint32_t smem_u32(const void* p) {
    uint32_t a;
    asm("{ .reg .u64 t; cvta.to.shared.u64 t, %1; cvt.u32.u64 %0, t; }"
        : "=r"(a) : "l"(p));
    return a;
}
__device__ __forceinline__ void ldm_x4(uint32_t* r, uint32_t addr) {
    asm volatile("ldmatrix.sync.aligned.m8n8.x4.shared.b16 {%0,%1,%2,%3}, [%4];"
        : "=r"(r[0]), "=r"(r[1]), "=r"(r[2]), "=r"(r[3]) : "r"(addr));
}
__device__ __forceinline__ void mma_bf16(float* c, const uint32_t* a,
                                         const uint32_t* b) {
    asm volatile(
        "mma.sync.aligned.m16n8k16.row.col.f32.bf16.bf16.f32 "
        "{%0,%1,%2,%3}, {%4,%5,%6,%7}, {%8,%9}, {%0,%1,%2,%3};"
        : "+f"(c[0]), "+f"(c[1]), "+f"(c[2]), "+f"(c[3])
        : "r"(a[0]), "r"(a[1]), "r"(a[2]), "r"(a[3]), "r"(b[0]), "r"(b[1]));
}
__device__ __forceinline__ float ex2f(float x) {
    float r;
    asm("ex2.approx.f32 %0, %1;" : "=f"(r) : "f"(x));
    return r;
}
__device__ __forceinline__ void split_pack(float a, float b,
                                           uint32_t& hi, uint32_t& lo) {
    __nv_bfloat162 h = __floats2bfloat162_rn(a, b);
    __nv_bfloat162 l = __floats2bfloat162_rn(a - __low2float(h),
                                             b - __high2float(h));
    hi = *(uint32_t*)&h;
    lo = *(uint32_t*)&l;
}
#define CP16(dst, src) \
    asm volatile("cp.async.cg.shared.global [%0], [%1], 16;" \
                 :: "r"(dst), "l"(src))
#define CP_COMMIT()  asm volatile("cp.async.commit_group;" ::: "memory")
#define CP_WAIT0()   asm volatile("cp.async.wait_group 0;" ::: "memory")

// ---------------------------------------------------------------------------
// Fused: x -> bf16 hi/lo conversion  +  s=16 pooling (cells partition pixels).
// grid (256 cells, 8 b), block 192: thread = channel pair (2c, 2c+1).
// ---------------------------------------------------------------------------
__global__ void conv_pool16_kernel(const float* __restrict__ x)
{
    const int c    = threadIdx.x * 2;
    const int cell = blockIdx.x;
    const int b    = blockIdx.y;
    const int ci = cell >> 4, cj = cell & 15;

    float s0 = 0.f, s1 = 0.f;
    #pragma unroll
    for (int dy = 0; dy < 4; dy++)
        #pragma unroll
        for (int dx = 0; dx < 4; dx++) {
            int n = (ci * 4 + dy) * HW + (cj * 4 + dx);
            size_t e = (size_t)(b * NPIX + n) * C_ + c;
            float2 v = *(const float2*)&x[e];
            uint32_t hi, lo;
            split_pack(v.x, v.y, hi, lo);
            ((uint32_t*)g_xhi)[e >> 1] = hi;
            ((uint32_t*)g_xlo)[e >> 1] = lo;
            s0 += v.x; s1 += v.y;
        }
    float2 o = make_float2(s0 * (1.f / 16.f), s1 * (1.f / 16.f));
    *(float2*)&g_xp[(size_t)(b * LP + 21 + cell) * C_ + c] = o;
}

// ---------------------------------------------------------------------------
// Fused pooled-x finisher: rows 0..20 (s1/s2/s4) computed on the fly from the
// s16 cells (exact: equal-size means of means); all 288 rows converted to
// bf16 hi/lo. One float4 per thread. Pad rows (>=277) read zero-init g_xp.
// ---------------------------------------------------------------------------
__global__ void conv_xp_kernel()
{
    const int i   = blockIdx.x * blockDim.x + threadIdx.x;  // float4 index
    const int row = i / 96;                                  // 96 float4 per row
    const int u   = i % 96;
    const int b   = row / LP, l = row % LP;

    float4 v;
    if (l >= 21) {
        v = ((const float4*)g_xp)[i];
    } else {
        const float4* base = (const float4*)(g_xp + (size_t)b * LP * C_);
        int ci0, ce, cj0;
        float inv;
        if (l == 0)      { ci0 = 0;                 cj0 = 0;                 ce = 16; inv = 1.f / 256.f; }
        else if (l < 5)  { int s = l - 1; ci0 = (s >> 1) * 8; cj0 = (s & 1) * 8; ce = 8; inv = 1.f / 64.f; }
        else             { int s = l - 5; ci0 = (s >> 2) * 4; cj0 = (s & 3) * 4; ce = 4; inv = 1.f / 16.f; }
        float4 s = make_float4(0.f, 0.f, 0.f, 0.f);
        for (int ci = ci0; ci < ci0 + ce; ci++)
            for (int cj = cj0; cj < cj0 + ce; cj++) {
                float4 t = base[(21 + ci * 16 + cj) * 96 + u];
                s.x += t.x; s.y += t.y; s.z += t.z; s.w += t.w;
            }
        v = make_float4(s.x * inv, s.y * inv, s.z * inv, s.w * inv);
    }

    uint32_t h0, l0, h1, l1;
    split_pack(v.x, v.y, h0, l0);
    split_pack(v.z, v.w, h1, l1);
    ((uint32_t*)g_xphi)[i * 2    ] = h0;
    ((uint32_t*)g_xphi)[i * 2 + 1] = h1;
    ((uint32_t*)g_xplo)[i * 2    ] = l0;
    ((uint32_t*)g_xplo)[i * 2 + 1] = l1;
}

// ---------------------------------------------------------------------------
// Tiled-transpose weight conversion: w[K,N] -> wT[N,K] bf16 hi/lo, coalesced
// both ways. QSC folded into the q-columns (n < 384) of w_qkv.
// grid 576 (432 wqkv tiles + 144 wp tiles), block (32, 8).
// ---------------------------------------------------------------------------
__global__ void conv_wT_kernel(const float* __restrict__ wqkv,
                               const float* __restrict__ wp)
{
    __shared__ float ts[32][33];
    int t = blockIdx.x;
    const float* src;
    __nv_bfloat16 *dh, *dl;
    int N;
    bool isq;
    if (t < 432) { src = wqkv; N = QKN; dh = g_wqT_hi; dl = g_wqT_lo; isq = true; }
    else         { t -= 432; src = wp; N = C_; dh = g_wpT_hi; dl = g_wpT_lo; isq = false; }

    const int tn = t % (N / 32), tk = t / (N / 32);
    const int tx = threadIdx.x, ty = threadIdx.y;

    #pragma unroll
    for (int it = 0; it < 4; it++) {
        int k = tk * 32 + ty + it * 8;
        ts[ty + it * 8][tx] = src[(size_t)k * N + tn * 32 + tx];
    }
    __syncthreads();

    #pragma unroll
    for (int it = 0; it < 4; it++) {
        int n = tn * 32 + ty + it * 8;
        int k = tk * 32 + tx;
        float v = ts[tx][ty + it * 8];
        if (isq && n < C_) v *= QSC;          // fold softmax scale into Wq
        __nv_bfloat16 h = __float2bfloat16(v);
        dh[(size_t)n * C_ + k] = h;
        dl[(size_t)n * C_ + k] = __float2bfloat16(v - __bfloat162float(h));
    }
}

// ---------------------------------------------------------------------------
// Tensor-core GEMM, cp.async 2-stage double-buffered.
//   C = A[*,384] * B^T, B stored [N,384]
// Block 128x128, 8 warps (4x2), warp tile 32x64, BK = 32, 12 K-chunks.
// Split-term mmas issued TERM-MAJOR: 16 independent mmas between successive
// updates of any accumulator (kills the RAW-latency stall seen at tensor=38%).
// Per-accumulator update order (hh, hl, lh per k-step) unchanged -> bit-identical.
// mode 0: A = g_x (32768 rows), B = wqT cols 0..383     -> q bf16 split
// mode 2: A = g_xp (2304 rows), B = wqT cols 384..1151  -> kp/vp scatter
// mode 1: A = g_ao (32768 rows), B = wpT                -> Cout + bias
// ---------------------------------------------------------------------------
#define TILE_B  10240      // one 128-row tile, bytes
#define GSTG    (4 * TILE_B)
#define GEMM_SMEM (2 * GSTG)      // 81920 B

__global__ void __launch_bounds__(256) gemm_mma_kernel(
    float* __restrict__ Cout, const float* __restrict__ bias, int mode)
{
    extern __shared__ char gsm[];

    const int tid  = threadIdx.x;
    const int lane = tid & 31;
    const int wid  = tid >> 5;
    const int wm   = wid & 3;
    const int wn   = wid >> 2;

    const __nv_bfloat16* Ahi = (mode == 0) ? g_xhi : (mode == 2) ? g_xphi : g_aohi;
    const __nv_bfloat16* Alo = (mode == 0) ? g_xlo : (mode == 2) ? g_xplo : g_aolo;
    const __nv_bfloat16* Bhi = (mode == 1) ? g_wpT_hi : g_wqT_hi;
    const __nv_bfloat16* Blo = (mode == 1) ? g_wpT_lo : g_wqT_lo;
    const int bcol0 = (mode == 2) ? C_ : 0;

    const int row0 = blockIdx.y * 128;
    const int col0 = blockIdx.x * 128;

    const int r0 = (tid * 2)     >> 2, q0 = (tid * 2)     & 3;
    const int r1 = (tid * 2 + 1) >> 2, q1 = (tid * 2 + 1) & 3;

    auto issue_chunk = [&](int c, int stg) {
        const int koff = c * 32;
        char* sb = gsm + stg * GSTG;
        {
            size_t gA = (size_t)(row0 + r0) * C_ + koff + q0 * 8;
            size_t gB = (size_t)(bcol0 + col0 + r0) * C_ + koff + q0 * 8;
            uint32_t so = smem_u32(sb) + r0 * 80 + q0 * 16;
            CP16(so,              Ahi + gA);
            CP16(so + TILE_B,     Alo + gA);
            CP16(so + 2 * TILE_B, Bhi + gB);
            CP16(so + 3 * TILE_B, Blo + gB);
        }
        {
            size_t gA = (size_t)(row0 + r1) * C_ + koff + q1 * 8;
            size_t gB = (size_t)(bcol0 + col0 + r1) * C_ + koff + q1 * 8;
            uint32_t so = smem_u32(sb) + r1 * 80 + q1 * 16;
            CP16(so,              Ahi + gA);
            CP16(so + TILE_B,     Alo + gA);
            CP16(so + 2 * TILE_B, Bhi + gB);
            CP16(so + 3 * TILE_B, Blo + gB);
        }
        CP_COMMIT();
    };

    float acc[2][8][4];
    #pragma unroll
    for (int mt = 0; mt < 2; mt++)
        #pragma unroll
        for (int nt = 0; nt < 8; nt++)
            #pragma unroll
            for (int e = 0; e < 4; e++) acc[mt][nt][e] = 0.f;

    const int aRow = (lane & 15);
    const int aKof = (lane >> 4) * 8;
    const int bRow = (lane & 7) + ((lane >> 3) & 1) * 8;
    const int bKof = (lane >> 4) * 8;

    issue_chunk(0, 0);

    for (int c = 0; c < 12; c++) {
        CP_WAIT0();
        __syncthreads();
        if (c + 1 < 12) issue_chunk(c + 1, (c + 1) & 1);

        char* sb = gsm + (c & 1) * GSTG;
        const uint32_t sA  = smem_u32(sb);
        const uint32_t sB  = sA + 2 * TILE_B;

        #pragma unroll
        for (int ks = 0; ks < 2; ks++) {
            const int kk = ks * 16;
            uint32_t ah[2][4], al[2][4];
            #pragma unroll
            for (int mt = 0; mt < 2; mt++) {
                uint32_t so = (wm * 32 + mt * 16 + aRow) * 80 + (kk + aKof) * 2;
                ldm_x4(ah[mt], sA + so);
                ldm_x4(al[mt], sA + TILE_B + so);
            }
            uint32_t bh[8][2], bl[8][2];
            #pragma unroll
            for (int np = 0; np < 4; np++) {
                uint32_t so = (wn * 64 + np * 16 + bRow) * 80 + (kk + bKof) * 2;
                uint32_t t[4];
                ldm_x4(t, sB + so);
                bh[np * 2    ][0] = t[0]; bh[np * 2    ][1] = t[2];
                bh[np * 2 + 1][0] = t[1]; bh[np * 2 + 1][1] = t[3];
                ldm_x4(t, sB + TILE_B + so);
                bl[np * 2    ][0] = t[0]; bl[np * 2    ][1] = t[2];
                bl[np * 2 + 1][0] = t[1]; bl[np * 2 + 1][1] = t[3];
            }
            // term-major: 16 independent mmas per term -> no RAW stalls
            #pragma unroll
            for (int mt = 0; mt < 2; mt++)
                #pragma unroll
                for (int nt = 0; nt < 8; nt++)
                    mma_bf16(acc[mt][nt], ah[mt], bh[nt]);
            #pragma unroll
            for (int mt = 0; mt < 2; mt++)
                #pragma unroll
                for (int nt = 0; nt < 8; nt++)
                    mma_bf16(acc[mt][nt], ah[mt], bl[nt]);
            #pragma unroll
            for (int mt = 0; mt < 2; mt++)
                #pragma unroll
                for (int nt = 0; nt < 8; nt++)
                    mma_bf16(acc[mt][nt], al[mt], bh[nt]);
        }
    }

    // ---- epilogue ----
    const int mrow = row0 + wm * 32 + (lane >> 2);
    const int ncol = wn * 64 + (lane & 3) * 2;

    if (mode == 0) {
        #pragma unroll
        for (int mt = 0; mt < 2; mt++)
            #pragma unroll
            for (int nt = 0; nt < 8; nt++) {
                int r  = mrow + mt * 16;
                int cc = col0 + ncol + nt * 8;
                uint32_t h0, l0, h1, l1;
                split_pack(acc[mt][nt][0], acc[mt][nt][1], h0, l0);
                split_pack(acc[mt][nt][2], acc[mt][nt][3], h1, l1);
                *(uint32_t*)&g_qhi[(size_t)r * C_ + cc]       = h0;
                *(uint32_t*)&g_qlo[(size_t)r * C_ + cc]       = l0;
                *(uint32_t*)&g_qhi[(size_t)(r + 8) * C_ + cc] = h1;
                *(uint32_t*)&g_qlo[(size_t)(r + 8) * C_ + cc] = l1;
            }
        return;
    }

    if (mode == 2) {
        #pragma unroll
        for (int mt = 0; mt < 2; mt++)
            #pragma unroll
            for (int nt = 0; nt < 8; nt++) {
                int gc = col0 + ncol + nt * 8;       // 0..767
                int t  = gc / C_;                    // 0 -> kp, 1 -> vp
                int cc = gc - t * C_;
                int hh = cc / HD, d = cc % HD;       // d is even
                #pragma unroll
                for (int half = 0; half < 2; half++) {
                    int r = mrow + mt * 16 + half * 8;
                    int b = r / LP, l = r % LP;
                    float a0 = acc[mt][nt][half * 2 + 0];
                    float a1 = acc[mt][nt][half * 2 + 1];
                    if (t == 0) {
                        uint32_t hi, lo;
                        split_pack(a0, a1, hi, lo);
                        size_t o = ((size_t)(b * NH + hh) * LP + l) * HD + d;
                        *(uint32_t*)&g_kphi[o] = hi;
                        *(uint32_t*)&g_kplo[o] = lo;
                    } else {
                        __nv_bfloat16 b0 = __float2bfloat16(a0);
                        __nv_bfloat16 b1 = __float2bfloat16(a1);
                        size_t o0 = ((size_t)(b * NH + hh) * HD + d)     * LP + l;
                        size_t o1 = ((size_t)(b * NH + hh) * HD + d + 1) * LP + l;
                        g_vpthi[o0] = b0;
                        g_vptlo[o0] = __float2bfloat16(a0 - __bfloat162float(b0));
                        g_vpthi[o1] = b1;
                        g_vptlo[o1] = __float2bfloat16(a1 - __bfloat162float(b1));
                    }
                }
            }
        return;
    }

    // mode 1: projection output + bias
    #pragma unroll
    for (int mt = 0; mt < 2; mt++)
        #pragma unroll
        for (int nt = 0; nt < 8; nt++) {
            int r  = mrow + mt * 16;
            int cc = col0 + ncol + nt * 8;
            float2 v0 = make_float2(acc[mt][nt][0] + bias[cc],
                                    acc[mt][nt][1] + bias[cc + 1]);
            float2 v1 = make_float2(acc[mt][nt][2] + bias[cc],
                                    acc[mt][nt][3] + bias[cc + 1]);
            *(float2*)&Cout[(size_t)r * C_ + cc]       = v0;
            *(float2*)&Cout[(size_t)(r + 8) * C_ + cc] = v1;
        }
}

// ---------------------------------------------------------------------------
// Tensor-core attention, 16 warps (512 threads): one CTA = one (b,h) x 256
// q rows; each warp owns 16 rows. Term-major mma issue (no RAW triplets).
// ---------------------------------------------------------------------------
#define QSTRIDE 56          // 48 + 8 pad  (conflict-free ldmatrix)
#define VSTRIDE 296         // 288 + 8 pad

#define SQH 0
#define SQL (SQH + 256 * QSTRIDE * 2)
#define SKH (SQL + 256 * QSTRIDE * 2)
#define SKL (SKH + LP * QSTRIDE * 2)
#define SVH (SKL + LP * QSTRIDE * 2)
#define SVL (SVH + HD * VSTRIDE * 2)
#define ATTN_SMEM (SVL + HD * VSTRIDE * 2)    // 178688 B

__global__ void __launch_bounds__(512, 1) attn_mma_kernel()
{
    extern __shared__ char sm[];

    const int tid  = threadIdx.x;
    const int lane = tid & 31;
    const int wid  = tid >> 5;          // 0..15, each warp = 16 q rows
    const int bh   = blockIdx.y;
    const int b    = bh >> 3, h = bh & 7;
    const int n0   = blockIdx.x * 256;

    // ---- prologue: stage Q, KP, VPt into SMEM via cp.async ----
    {
        const uint4* qh = (const uint4*)(g_qhi + (size_t)(b * NPIX + n0) * C_ + h * HD);
        const uint4* ql = (const uint4*)(g_qlo + (size_t)(b * NPIX + n0) * C_ + h * HD);
        const uint32_t sbase = smem_u32(sm);
        for (int i = tid; i < 256 * 6; i += 512) {
            int r = i / 6, u = i % 6;
            CP16(sbase + SQH + r * (QSTRIDE * 2) + u * 16, qh + r * 48 + u);
            CP16(sbase + SQL + r * (QSTRIDE * 2) + u * 16, ql + r * 48 + u);
        }
        const uint4* kh = (const uint4*)(g_kphi + (size_t)bh * LP * HD);
        const uint4* kl = (const uint4*)(g_kplo + (size_t)bh * LP * HD);
        for (int i = tid; i < LP * 6; i += 512) {
            int r = i / 6, u = i % 6;
            CP16(sbase + SKH + r * (QSTRIDE * 2) + u * 16, kh + i);
            CP16(sbase + SKL + r * (QSTRIDE * 2) + u * 16, kl + i);
        }
        const uint4* vh = (const uint4*)(g_vpthi + (size_t)bh * HD * LP);
        const uint4* vl = (const uint4*)(g_vptlo + (size_t)bh * HD * LP);
        for (int i = tid; i < HD * 36; i += 512) {
            int r = i / 36, u = i % 36;
            CP16(sbase + SVH + r * (VSTRIDE * 2) + u * 16, vh + i);
            CP16(sbase + SVL + r * (VSTRIDE * 2) + u * 16, vl + i);
        }
        CP_COMMIT();
        CP_WAIT0();
    }
    __syncthreads();

    const int aRow = (lane & 15);
    const int aKof = (lane >> 4) * 8;
    const int bRow = (lane & 7) + ((lane >> 3) & 1) * 8;
    const int bKof = (lane >> 4) * 8;

    // ---- Q fragments: this warp's 16 rows, all 48 dims ----
    uint32_t qh[3][4], ql[3][4];
    #pragma unroll
    for (int ks = 0; ks < 3; ks++) {
        int so = (wid * 16 + aRow) * (QSTRIDE * 2) + (ks * 16 + aKof) * 2;
        ldm_x4(qh[ks], smem_u32(sm + SQH + so));
        ldm_x4(ql[ks], smem_u32(sm + SQL + so));
    }

    float o[6][4];
    #pragma unroll
    for (int nt = 0; nt < 6; nt++)
        #pragma unroll
        for (int e = 0; e < 4; e++) o[nt][e] = 0.f;
    float rs[2] = {0.f, 0.f};

    for (int chunk = 0; chunk < 9; chunk++) {
        // ---- S = Q * KP^T over 32 L-columns ----
        float s[4][4];
        #pragma unroll
        for (int nt = 0; nt < 4; nt++)
            #pragma unroll
            for (int e = 0; e < 4; e++) s[nt][e] = 0.f;

        #pragma unroll
        for (int ks = 0; ks < 3; ks++) {
            uint32_t kbh[4][2], kbl[4][2];
            #pragma unroll
            for (int np = 0; np < 2; np++) {
                int so = (chunk * 32 + np * 16 + bRow) * (QSTRIDE * 2)
                       + (ks * 16 + bKof) * 2;
                uint32_t t[4];
                ldm_x4(t, smem_u32(sm + SKH + so));
                kbh[np * 2    ][0] = t[0]; kbh[np * 2    ][1] = t[2];
                kbh[np * 2 + 1][0] = t[1]; kbh[np * 2 + 1][1] = t[3];
                ldm_x4(t, smem_u32(sm + SKL + so));
                kbl[np * 2    ][0] = t[0]; kbl[np * 2    ][1] = t[2];
                kbl[np * 2 + 1][0] = t[1]; kbl[np * 2 + 1][1] = t[3];
            }
            // term-major (4 independent mmas between RAW updates)
            #pragma unroll
            for (int nt = 0; nt < 4; nt++) mma_bf16(s[nt], qh[ks], kbh[nt]);
            #pragma unroll
            for (int nt = 0; nt < 4; nt++) mma_bf16(s[nt], qh[ks], kbl[nt]);
            #pragma unroll
            for (int nt = 0; nt < 4; nt++) mma_bf16(s[nt], ql[ks], kbh[nt]);
        }

        // ---- softmax numerator: e = 2^s, masked past L_, row sums ----
        #pragma unroll
        for (int nt = 0; nt < 4; nt++)
            #pragma unroll
            for (int e = 0; e < 4; e++) {
                float v = ex2f(s[nt][e]);
                if (chunk == 8) {
                    int col = 256 + nt * 8 + (lane & 3) * 2 + (e & 1);
                    if (col >= L_) v = 0.f;
                }
                s[nt][e] = v;
                rs[e >> 1] += v;
            }

        // ---- O += P * VP  (P from S-fragments, register-level repack) ----
        #pragma unroll
        for (int ks2 = 0; ks2 < 2; ks2++) {
            uint32_t ph[4], pl[4];
            split_pack(s[2 * ks2][0],     s[2 * ks2][1],     ph[0], pl[0]);
            split_pack(s[2 * ks2][2],     s[2 * ks2][3],     ph[1], pl[1]);
            split_pack(s[2 * ks2 + 1][0], s[2 * ks2 + 1][1], ph[2], pl[2]);
            split_pack(s[2 * ks2 + 1][2], s[2 * ks2 + 1][3], ph[3], pl[3]);

            uint32_t vbh[6][2], vbl[6][2];
            #pragma unroll
            for (int np = 0; np < 3; np++) {
                int so = (np * 16 + bRow) * (VSTRIDE * 2)
                       + (chunk * 32 + ks2 * 16 + bKof) * 2;
                uint32_t t[4];
                ldm_x4(t, smem_u32(sm + SVH + so));
                vbh[np * 2    ][0] = t[0]; vbh[np * 2    ][1] = t[2];
                vbh[np * 2 + 1][0] = t[1]; vbh[np * 2 + 1][1] = t[3];
                ldm_x4(t, smem_u32(sm + SVL + so));
                vbl[np * 2    ][0] = t[0]; vbl[np * 2    ][1] = t[2];
                vbl[np * 2 + 1][0] = t[1]; vbl[np * 2 + 1][1] = t[3];
            }
            // term-major (6 independent mmas between RAW updates)
            #pragma unroll
            for (int nt = 0; nt < 6; nt++) mma_bf16(o[nt], ph, vbh[nt]);
            #pragma unroll
            for (int nt = 0; nt < 6; nt++) mma_bf16(o[nt], ph, vbl[nt]);
            #pragma unroll
            for (int nt = 0; nt < 6; nt++) mma_bf16(o[nt], pl, vbh[nt]);
        }
    }

    // ---- finalize: reduce row sums across the 4 lanes of each row ----
    #pragma unroll
    for (int rhalf = 0; rhalf < 2; rhalf++) {
        float v = rs[rhalf];
        v += __shfl_xor_sync(0xFFFFFFFF, v, 1);
        v += __shfl_xor_sync(0xFFFFFFFF, v, 2);
        rs[rhalf] = 1.f / v;
    }

    // ---- write attention output as bf16 hi/lo for the projection GEMM ----
    const int rbase = n0 + wid * 16 + (lane >> 2);
    #pragma unroll
    for (int nt = 0; nt < 6; nt++) {
        int cc = h * HD + nt * 8 + (lane & 3) * 2;
        uint32_t h0, l0, h1, l1;
        split_pack(o[nt][0] * rs[0], o[nt][1] * rs[0], h0, l0);
        split_pack(o[nt][2] * rs[1], o[nt][3] * rs[1], h1, l1);
        size_t r0o = (size_t)(b * NPIX + rbase) * C_ + cc;
        size_t r1o = (size_t)(b * NPIX + rbase + 8) * C_ + cc;
        *(uint32_t*)&g_aohi[r0o] = h0;
        *(uint32_t*)&g_aolo[r0o] = l0;
        *(uint32_t*)&g_aohi[r1o] = h1;
        *(uint32_t*)&g_aolo[r1o] = l1;
    }
}

// ---------------------------------------------------------------------------
// Entry point
// ---------------------------------------------------------------------------
extern "C" void kernel_launch(void* const* d_in, const int* in_sizes, int n_in,
                              void* d_out, int out_size)
{
    const float* x      = (const float*)d_in[0];
    const float* w_qkv  = (const float*)d_in[1];
    const float* w_proj = (const float*)d_in[2];
    const float* b_proj = (const float*)d_in[3];
    float* out = (float*)d_out;

    cudaFuncSetAttribute(attn_mma_kernel,
                         cudaFuncAttributeMaxDynamicSharedMemorySize,
                         ATTN_SMEM);
    cudaFuncSetAttribute(gemm_mma_kernel,
                         cudaFuncAttributeMaxDynamicSharedMemorySize,
                         GEMM_SMEM);

    // 0) conversions + pooling (pooling commutes with K/V projection)
    conv_wT_kernel<<<576, dim3(32, 8)>>>(w_qkv, w_proj);
    conv_pool16_kernel<<<dim3(256, B_), 192>>>(x);
    conv_xp_kernel<<<(MP_ * C_ / 4) / 256, 256>>>();

    // 1) Q GEMM (32768 x 384 x 384) -> q bf16 split (scale folded in weights)
    gemm_mma_kernel<<<dim3(3, M_ / 128), 256, GEMM_SMEM>>>(nullptr, nullptr, 0);

    // 2) K/V GEMM on pooled rows (2304 x 768 x 384) -> kp / vp (transposed)
    gemm_mma_kernel<<<dim3(6, MP_ / 128), 256, GEMM_SMEM>>>(nullptr, nullptr, 2);

    // 3) tensor-core attention, 16 warps (writes ao hi/lo bf16)
    attn_mma_kernel<<<dim3(NPIX / 256, B_ * NH), 512, ATTN_SMEM>>>();

    // 4) projection + bias -> d_out
    gemm_mma_kernel<<<dim3(3, M_ / 128), 256, GEMM_SMEM>>>(out, b_proj, 1);
}